// round 4
// baseline (speedup 1.0000x reference)
#include <cuda_runtime.h>
#include <math_constants.h>

#define B_  8
#define H_  8
#define M_  512
#define N_  512
#define DD  64
#define HID 16

#define BM 64
#define BN 64
#define TM 2
#define TN 8
#define THREADS 256

// smem strides (words)
#define QS 68   // 16B-aligned rows; 68%32=4 spreads rows across banks
#define KS 68
#define VS 68
#define PS 72   // 16B-aligned so P rows can be read as LDS.128

typedef unsigned long long ull;

__device__ __forceinline__ ull fma2(ull a, ull b, ull c) {
    ull d; asm("fma.rn.f32x2 %0,%1,%2,%3;" : "=l"(d) : "l"(a), "l"(b), "l"(c)); return d;
}
__device__ __forceinline__ ull mul2(ull a, ull b) {
    ull d; asm("mul.rn.f32x2 %0,%1,%2;" : "=l"(d) : "l"(a), "l"(b)); return d;
}
__device__ __forceinline__ ull pk(float x, float y) {
    ull r; asm("mov.b64 %0,{%1,%2};" : "=l"(r) : "f"(x), "f"(y)); return r;
}
__device__ __forceinline__ void upk(ull a, float& x, float& y) {
    asm("mov.b64 {%0,%1},%2;" : "=f"(x), "=f"(y) : "l"(a));
}
__device__ __forceinline__ ull relu2(ull a) {
    float x, y; upk(a, x, y);
    x = fmaxf(x, 0.0f); y = fmaxf(y, 0.0f);
    return pk(x, y);
}

__global__ __launch_bounds__(THREADS, 2)
void msdpa_kernel(const float* __restrict__ q,
                  const float* __restrict__ k,
                  const float* __restrict__ v,
                  const float* __restrict__ dmat,
                  const float* __restrict__ mixW1,
                  const float* __restrict__ mixb1,
                  const float* __restrict__ mixW2,
                  const float* __restrict__ mixb2,
                  float* __restrict__ out)
{
    extern __shared__ float smem[];
    float* Qs = smem;                 // [BM][QS]
    float* Ks = Qs + BM * QS;         // [BN][KS]
    float* Vs = Ks + BN * KS;         // [BN][VS]
    float* Ps = Vs + BN * VS;         // [BM][PS]

    // packed MLP weights: per f: {w1s*scale dup, w1d dup, b1 dup, w2 dup}
    __shared__ __align__(16) float sWp[HID * 8];
    __shared__ float sB2;

    const int tid = threadIdx.x;
    const int tx  = tid & 7;      // 0..7
    const int ty  = tid >> 3;     // 0..31  (rows ty*2+i)

    const int b  = blockIdx.z;
    const int h  = blockIdx.y;
    const int m0 = blockIdx.x * BM;

    const float* qb = q + ((size_t)(b * H_ + h) * M_ + m0) * DD;
    const float* kb = k + (size_t)(b * H_ + h) * N_ * DD;
    const float* vb = v + (size_t)(b * H_ + h) * N_ * DD;
    const float* db = dmat + ((size_t)b * M_ + m0) * N_;

    if (tid < HID) {
        const float scale = 0.125f;   // 1/sqrt(64), folded into score-channel W1
        float a = mixW1[(h * 2 + 0) * HID + tid] * scale;
        float c = mixW1[(h * 2 + 1) * HID + tid];
        float e = mixb1[h * HID + tid];
        float w = mixW2[h * HID + tid];
        float* wp = sWp + tid * 8;
        wp[0] = a; wp[1] = a;
        wp[2] = c; wp[3] = c;
        wp[4] = e; wp[5] = e;
        wp[6] = w; wp[7] = w;
    }
    if (tid == 0) sB2 = mixb2[h];

    // Load Q tile [BM][DD] -> Qs
    #pragma unroll
    for (int r = 0; r < 4; r++) {
        int idx = tid + r * THREADS;       // 0..1023 float4 units
        int row = idx >> 4;
        int d4  = (idx & 15) << 2;
        *(float4*)(Qs + row * QS + d4) = *(const float4*)(qb + row * DD + d4);
    }

    // accumulators: O packed over adjacent output-col pairs (cols 2tx+16j2+{0,1})
    ull Oacc2[TM][4];
    float rmax[TM], rsum[TM];
    #pragma unroll
    for (int i = 0; i < TM; i++) {
        rmax[i] = -CUDART_INF_F;
        rsum[i] = 0.0f;
        #pragma unroll
        for (int j2 = 0; j2 < 4; j2++) Oacc2[i][j2] = 0ull;
    }

    __syncthreads();

    const unsigned FULL = 0xffffffffu;
    const float B2 = sB2;

    for (int t = 0; t < N_ / BN; t++) {
        // ---- stage K, V tiles ----
        const float* kt = kb + (size_t)t * BN * DD;
        const float* vt = vb + (size_t)t * BN * DD;
        #pragma unroll
        for (int r = 0; r < 4; r++) {
            int idx = tid + r * THREADS;
            int row = idx >> 4;
            int d4  = (idx & 15) << 2;
            *(float4*)(Ks + row * KS + d4) = *(const float4*)(kt + row * DD + d4);
            *(float4*)(Vs + row * VS + d4) = *(const float4*)(vt + row * DD + d4);
        }
        __syncthreads();

        // ---- S = Q K^T, accumulated in d-parity pairs (FFMA2) ----
        // S cols for this thread: tx + 8*j, j=0..7
        ull s2[TM][TN];
        #pragma unroll
        for (int i = 0; i < TM; i++)
            #pragma unroll
            for (int j = 0; j < TN; j++) s2[i][j] = 0ull;

        #pragma unroll 4
        for (int d4 = 0; d4 < DD; d4 += 4) {
            ulonglong2 qv[TM], kv[TN];
            #pragma unroll
            for (int i = 0; i < TM; i++)
                qv[i] = *(const ulonglong2*)(Qs + (ty * TM + i) * QS + d4);
            #pragma unroll
            for (int j = 0; j < TN; j++)
                kv[j] = *(const ulonglong2*)(Ks + (tx + 8 * j) * KS + d4);
            #pragma unroll
            for (int i = 0; i < TM; i++)
                #pragma unroll
                for (int j = 0; j < TN; j++) {
                    s2[i][j] = fma2(qv[i].x, kv[j].x, s2[i][j]);
                    s2[i][j] = fma2(qv[i].y, kv[j].y, s2[i][j]);
                }
        }

        // ---- reduce pairs, fetch dmat, packed MLP ----
        // packed lane pairs hold S columns (tx+16j2, tx+8+16j2)
        ull ms2[TM][4], dm2[TM][4], acc2[TM][4];
        const ull b2p = pk(B2, B2);
        #pragma unroll
        for (int i = 0; i < TM; i++) {
            #pragma unroll
            for (int j2 = 0; j2 < 4; j2++) {
                float x0, y0, x1, y1;
                upk(s2[i][2 * j2],     x0, y0);   // col tx + 16*j2
                upk(s2[i][2 * j2 + 1], x1, y1);   // col tx + 8 + 16*j2
                ms2[i][j2] = pk(x0 + y0, x1 + y1);
            }
            const float* drow = db + (size_t)(ty * TM + i) * N_ + t * BN + tx;
            #pragma unroll
            for (int j2 = 0; j2 < 4; j2++)
                dm2[i][j2] = pk(drow[(2 * j2) * 8], drow[(2 * j2 + 1) * 8]);
            #pragma unroll
            for (int j2 = 0; j2 < 4; j2++) acc2[i][j2] = b2p;
        }

        #pragma unroll 4
        for (int f = 0; f < HID; f++) {
            const ull a2 = *(const ull*)(sWp + f * 8 + 0);
            const ull c2 = *(const ull*)(sWp + f * 8 + 2);
            const ull e2 = *(const ull*)(sWp + f * 8 + 4);
            const ull w2 = *(const ull*)(sWp + f * 8 + 6);
            #pragma unroll
            for (int i = 0; i < TM; i++)
                #pragma unroll
                for (int j2 = 0; j2 < 4; j2++) {
                    ull t2 = fma2(a2, ms2[i][j2], fma2(c2, dm2[i][j2], e2));
                    acc2[i][j2] = fma2(w2, relu2(t2), acc2[i][j2]);
                }
        }

        // ---- online softmax per row; write P at its TRUE columns tx+8j ----
        #pragma unroll
        for (int i = 0; i < TM; i++) {
            float p[TN];
            #pragma unroll
            for (int j2 = 0; j2 < 4; j2++)
                upk(acc2[i][j2], p[2 * j2], p[2 * j2 + 1]);
            // p[2j2]   -> col tx + 16*j2      (= tx + 8*(2j2))
            // p[2j2+1] -> col tx + 8 + 16*j2  (= tx + 8*(2j2+1))

            float mx = p[0];
            #pragma unroll
            for (int j = 1; j < TN; j++) mx = fmaxf(mx, p[j]);
            mx = fmaxf(mx, __shfl_xor_sync(FULL, mx, 1, 8));
            mx = fmaxf(mx, __shfl_xor_sync(FULL, mx, 2, 8));
            mx = fmaxf(mx, __shfl_xor_sync(FULL, mx, 4, 8));

            float nm   = fmaxf(rmax[i], mx);
            float corr = __expf(rmax[i] - nm);
            rmax[i] = nm;

            float ls = 0.0f;
            #pragma unroll
            for (int j = 0; j < TN; j++) {
                p[j] = __expf(p[j] - nm);
                ls += p[j];
            }
            ls += __shfl_xor_sync(FULL, ls, 1, 8);
            ls += __shfl_xor_sync(FULL, ls, 2, 8);
            ls += __shfl_xor_sync(FULL, ls, 4, 8);
            rsum[i] = rsum[i] * corr + ls;

            const ull c2 = pk(corr, corr);
            #pragma unroll
            for (int j2 = 0; j2 < 4; j2++)
                Oacc2[i][j2] = mul2(Oacc2[i][j2], c2);

            float* prow = Ps + (ty * TM + i) * PS;
            #pragma unroll
            for (int j = 0; j < TN; j++)
                prow[tx + 8 * j] = p[j];
        }
        __syncthreads();

        // ---- O += P @ V : P rows read as LDS.128 (4 n at a time) ----
        #pragma unroll 2
        for (int n4 = 0; n4 < BN; n4 += 4) {
            float4 pr[TM];
            #pragma unroll
            for (int i = 0; i < TM; i++)
                pr[i] = *(const float4*)(Ps + (ty * TM + i) * PS + n4);
            float pa[TM][4];
            #pragma unroll
            for (int i = 0; i < TM; i++) {
                pa[i][0] = pr[i].x; pa[i][1] = pr[i].y;
                pa[i][2] = pr[i].z; pa[i][3] = pr[i].w;
            }
            #pragma unroll
            for (int s = 0; s < 4; s++) {
                const int n = n4 + s;
                ull vv[4];
                #pragma unroll
                for (int j2 = 0; j2 < 4; j2++)
                    vv[j2] = *(const ull*)(Vs + n * VS + tx * 2 + 16 * j2);
                #pragma unroll
                for (int i = 0; i < TM; i++) {
                    ull pp = pk(pa[i][s], pa[i][s]);
                    #pragma unroll
                    for (int j2 = 0; j2 < 4; j2++)
                        Oacc2[i][j2] = fma2(pp, vv[j2], Oacc2[i][j2]);
                }
            }
        }
        __syncthreads();
    }

    // ---- normalize + store (float2 stores; O cols 2tx+16j2+{0,1}) ----
    float* ob = out + ((size_t)(b * H_ + h) * M_ + m0) * DD;
    #pragma unroll
    for (int i = 0; i < TM; i++) {
        float inv = 1.0f / rsum[i];
        #pragma unroll
        for (int j2 = 0; j2 < 4; j2++) {
            float x, y; upk(Oacc2[i][j2], x, y);
            float2 o = make_float2(x * inv, y * inv);
            *(float2*)(ob + (size_t)(ty * TM + i) * DD + tx * 2 + 16 * j2) = o;
        }
    }
}

extern "C" void kernel_launch(void* const* d_in, const int* in_sizes, int n_in,
                              void* d_out, int out_size)
{
    const float* q     = (const float*)d_in[0];
    const float* k     = (const float*)d_in[1];
    const float* v     = (const float*)d_in[2];
    const float* dmat  = (const float*)d_in[3];
    const float* mixW1 = (const float*)d_in[4];
    const float* mixb1 = (const float*)d_in[5];
    const float* mixW2 = (const float*)d_in[6];
    const float* mixb2 = (const float*)d_in[7];
    float* out = (float*)d_out;

    size_t smem_bytes = (size_t)(BM * QS + BN * KS + BN * VS + BM * PS) * sizeof(float);
    cudaFuncSetAttribute(msdpa_kernel,
                         cudaFuncAttributeMaxDynamicSharedMemorySize,
                         (int)smem_bytes);

    dim3 grid(M_ / BM, H_, B_);   // (8, 8, 8)
    msdpa_kernel<<<grid, THREADS, smem_bytes>>>(q, k, v, dmat,
                                                mixW1, mixb1, mixW2, mixb2, out);
}

// round 5
// speedup vs baseline: 1.1562x; 1.1562x over previous
#include <cuda_runtime.h>
#include <math_constants.h>

#define B_  8
#define H_  8
#define M_  512
#define N_  512
#define DD  64
#define HID 16

#define BM 64
#define BN 64
#define TM 4
#define TN 8
#define THREADS 128

// smem strides (words)
#define QS 68   // 16B-aligned rows; 68%32=4 spreads rows across banks
#define KS 68
#define VS 68
#define PS 72   // 16B-aligned so P rows can be read as LDS.128

#define LOG2E 1.44269504088896340736f

typedef unsigned long long ull;

__device__ __forceinline__ ull fma2(ull a, ull b, ull c) {
    ull d; asm("fma.rn.f32x2 %0,%1,%2,%3;" : "=l"(d) : "l"(a), "l"(b), "l"(c)); return d;
}
__device__ __forceinline__ ull mul2(ull a, ull b) {
    ull d; asm("mul.rn.f32x2 %0,%1,%2;" : "=l"(d) : "l"(a), "l"(b)); return d;
}
__device__ __forceinline__ ull pk(float x, float y) {
    ull r; asm("mov.b64 %0,{%1,%2};" : "=l"(r) : "f"(x), "f"(y)); return r;
}
__device__ __forceinline__ void upk(ull a, float& x, float& y) {
    asm("mov.b64 {%0,%1},%2;" : "=f"(x), "=f"(y) : "l"(a));
}
__device__ __forceinline__ ull relu2(ull a) {
    float x, y; upk(a, x, y);
    x = fmaxf(x, 0.0f); y = fmaxf(y, 0.0f);
    return pk(x, y);
}

__global__ __launch_bounds__(THREADS, 3)
void msdpa_kernel(const float* __restrict__ q,
                  const float* __restrict__ k,
                  const float* __restrict__ v,
                  const float* __restrict__ dmat,
                  const float* __restrict__ mixW1,
                  const float* __restrict__ mixb1,
                  const float* __restrict__ mixW2,
                  const float* __restrict__ mixb2,
                  float* __restrict__ out)
{
    extern __shared__ float smem[];
    float* Qs = smem;                 // [BM][QS]
    float* Ks = Qs + BM * QS;         // [BN][KS]
    float* Vs = Ks + BN * KS;         // [BN][VS]
    float* Ps = Vs + BN * VS;         // [BM][PS]

    // packed MLP weights: per f: {w1s*scale dup, w1d dup, b1 dup, w2*log2e dup}
    __shared__ __align__(16) float sWp[HID * 8];
    __shared__ float sB2;

    const int tid = threadIdx.x;
    const int tx  = tid & 7;      // 0..7
    const int ty  = tid >> 3;     // 0..15  (rows ty*4+i)

    const int b  = blockIdx.z;
    const int h  = blockIdx.y;
    const int m0 = blockIdx.x * BM;

    const float* qb = q + ((size_t)(b * H_ + h) * M_ + m0) * DD;
    const float* kb = k + (size_t)(b * H_ + h) * N_ * DD;
    const float* vb = v + (size_t)(b * H_ + h) * N_ * DD;
    const float* db = dmat + ((size_t)b * M_ + m0) * N_;

    if (tid < HID) {
        const float scale = 0.125f;   // 1/sqrt(64), folded into score-channel W1
        float a = mixW1[(h * 2 + 0) * HID + tid] * scale;
        float c = mixW1[(h * 2 + 1) * HID + tid];
        float e = mixb1[h * HID + tid];
        float w = mixW2[h * HID + tid] * LOG2E;   // exp2-domain softmax
        float* wp = sWp + tid * 8;
        wp[0] = a; wp[1] = a;
        wp[2] = c; wp[3] = c;
        wp[4] = e; wp[5] = e;
        wp[6] = w; wp[7] = w;
    }
    if (tid == 0) sB2 = mixb2[h] * LOG2E;

    // Load Q tile [BM][DD] -> Qs
    #pragma unroll
    for (int r = 0; r < 8; r++) {
        int idx = tid + r * THREADS;       // 0..1023 float4 units
        int row = idx >> 4;
        int d4  = (idx & 15) << 2;
        *(float4*)(Qs + row * QS + d4) = *(const float4*)(qb + row * DD + d4);
    }

    // accumulators: O packed over adjacent output-col pairs (cols 2tx+16j2+{0,1})
    ull Oacc2[TM][4];
    float rmax[TM], rsum[TM];
    #pragma unroll
    for (int i = 0; i < TM; i++) {
        rmax[i] = -CUDART_INF_F;
        rsum[i] = 0.0f;
        #pragma unroll
        for (int j2 = 0; j2 < 4; j2++) Oacc2[i][j2] = 0ull;
    }

    __syncthreads();

    const unsigned FULL = 0xffffffffu;
    const float B2 = sB2;

    for (int t = 0; t < N_ / BN; t++) {
        // ---- stage K, V tiles ----
        const float* kt = kb + (size_t)t * BN * DD;
        const float* vt = vb + (size_t)t * BN * DD;
        #pragma unroll
        for (int r = 0; r < 8; r++) {
            int idx = tid + r * THREADS;
            int row = idx >> 4;
            int d4  = (idx & 15) << 2;
            *(float4*)(Ks + row * KS + d4) = *(const float4*)(kt + row * DD + d4);
            *(float4*)(Vs + row * VS + d4) = *(const float4*)(vt + row * DD + d4);
        }
        __syncthreads();

        // ---- S = Q K^T, accumulated in d-parity pairs (FFMA2) ----
        // S cols for this thread: tx + 8*j, j=0..7
        ull s2[TM][TN];
        #pragma unroll
        for (int i = 0; i < TM; i++)
            #pragma unroll
            for (int j = 0; j < TN; j++) s2[i][j] = 0ull;

        #pragma unroll 4
        for (int d4 = 0; d4 < DD; d4 += 4) {
            ulonglong2 qv[TM], kv[TN];
            #pragma unroll
            for (int i = 0; i < TM; i++)
                qv[i] = *(const ulonglong2*)(Qs + (ty * TM + i) * QS + d4);
            #pragma unroll
            for (int j = 0; j < TN; j++)
                kv[j] = *(const ulonglong2*)(Ks + (tx + 8 * j) * KS + d4);
            #pragma unroll
            for (int i = 0; i < TM; i++)
                #pragma unroll
                for (int j = 0; j < TN; j++) {
                    s2[i][j] = fma2(qv[i].x, kv[j].x, s2[i][j]);
                    s2[i][j] = fma2(qv[i].y, kv[j].y, s2[i][j]);
                }
        }

        // ---- reduce pairs, fetch dmat, packed MLP ----
        // packed lane pairs hold S columns (tx+16j2, tx+8+16j2)
        ull ms2[TM][4], dm2[TM][4], acc2[TM][4];
        const ull b2p = pk(B2, B2);
        #pragma unroll
        for (int i = 0; i < TM; i++) {
            #pragma unroll
            for (int j2 = 0; j2 < 4; j2++) {
                float x0, y0, x1, y1;
                upk(s2[i][2 * j2],     x0, y0);   // col tx + 16*j2
                upk(s2[i][2 * j2 + 1], x1, y1);   // col tx + 8 + 16*j2
                ms2[i][j2] = pk(x0 + y0, x1 + y1);
            }
            const float* drow = db + (size_t)(ty * TM + i) * N_ + t * BN + tx;
            #pragma unroll
            for (int j2 = 0; j2 < 4; j2++)
                dm2[i][j2] = pk(drow[(2 * j2) * 8], drow[(2 * j2 + 1) * 8]);
            #pragma unroll
            for (int j2 = 0; j2 < 4; j2++) acc2[i][j2] = b2p;
        }

        #pragma unroll 4
        for (int f = 0; f < HID; f++) {
            const ull a2 = *(const ull*)(sWp + f * 8 + 0);
            const ull c2 = *(const ull*)(sWp + f * 8 + 2);
            const ull e2 = *(const ull*)(sWp + f * 8 + 4);
            const ull w2 = *(const ull*)(sWp + f * 8 + 6);
            #pragma unroll
            for (int i = 0; i < TM; i++)
                #pragma unroll
                for (int j2 = 0; j2 < 4; j2++) {
                    ull t2 = fma2(a2, ms2[i][j2], fma2(c2, dm2[i][j2], e2));
                    acc2[i][j2] = fma2(w2, relu2(t2), acc2[i][j2]);
                }
        }

        // ---- online softmax per row (exp2 domain); write P at cols tx+8j ----
        #pragma unroll
        for (int i = 0; i < TM; i++) {
            float p[TN];
            #pragma unroll
            for (int j2 = 0; j2 < 4; j2++)
                upk(acc2[i][j2], p[2 * j2], p[2 * j2 + 1]);
            // p[2j2] -> col tx+16j2 (= tx+8*(2j2)), p[2j2+1] -> col tx+8+16j2

            float mx = p[0];
            #pragma unroll
            for (int j = 1; j < TN; j++) mx = fmaxf(mx, p[j]);
            mx = fmaxf(mx, __shfl_xor_sync(FULL, mx, 1, 8));
            mx = fmaxf(mx, __shfl_xor_sync(FULL, mx, 2, 8));
            mx = fmaxf(mx, __shfl_xor_sync(FULL, mx, 4, 8));

            float nm   = fmaxf(rmax[i], mx);
            float corr = exp2f(rmax[i] - nm);
            rmax[i] = nm;

            float ls = 0.0f;
            #pragma unroll
            for (int j = 0; j < TN; j++) {
                p[j] = exp2f(p[j] - nm);
                ls += p[j];
            }
            ls += __shfl_xor_sync(FULL, ls, 1, 8);
            ls += __shfl_xor_sync(FULL, ls, 2, 8);
            ls += __shfl_xor_sync(FULL, ls, 4, 8);
            rsum[i] = rsum[i] * corr + ls;

            const ull c2 = pk(corr, corr);
            #pragma unroll
            for (int j2 = 0; j2 < 4; j2++)
                Oacc2[i][j2] = mul2(Oacc2[i][j2], c2);

            float* prow = Ps + (ty * TM + i) * PS;
            #pragma unroll
            for (int j = 0; j < TN; j++)
                prow[tx + 8 * j] = p[j];
        }
        __syncthreads();

        // ---- O += P @ V : P rows read as LDS.128 (4 n at a time) ----
        #pragma unroll 2
        for (int n4 = 0; n4 < BN; n4 += 4) {
            float4 pr[TM];
            #pragma unroll
            for (int i = 0; i < TM; i++)
                pr[i] = *(const float4*)(Ps + (ty * TM + i) * PS + n4);
            float pa[TM][4];
            #pragma unroll
            for (int i = 0; i < TM; i++) {
                pa[i][0] = pr[i].x; pa[i][1] = pr[i].y;
                pa[i][2] = pr[i].z; pa[i][3] = pr[i].w;
            }
            #pragma unroll
            for (int s = 0; s < 4; s++) {
                const int n = n4 + s;
                ull vv[4];
                #pragma unroll
                for (int j2 = 0; j2 < 4; j2++)
                    vv[j2] = *(const ull*)(Vs + n * VS + tx * 2 + 16 * j2);
                #pragma unroll
                for (int i = 0; i < TM; i++) {
                    ull pp = pk(pa[i][s], pa[i][s]);
                    #pragma unroll
                    for (int j2 = 0; j2 < 4; j2++)
                        Oacc2[i][j2] = fma2(pp, vv[j2], Oacc2[i][j2]);
                }
            }
        }
        __syncthreads();
    }

    // ---- normalize + store (float2 stores; O cols 2tx+16j2+{0,1}) ----
    float* ob = out + ((size_t)(b * H_ + h) * M_ + m0) * DD;
    #pragma unroll
    for (int i = 0; i < TM; i++) {
        float inv = 1.0f / rsum[i];
        #pragma unroll
        for (int j2 = 0; j2 < 4; j2++) {
            float x, y; upk(Oacc2[i][j2], x, y);
            float2 o = make_float2(x * inv, y * inv);
            *(float2*)(ob + (size_t)(ty * TM + i) * DD + tx * 2 + 16 * j2) = o;
        }
    }
}

extern "C" void kernel_launch(void* const* d_in, const int* in_sizes, int n_in,
                              void* d_out, int out_size)
{
    const float* q     = (const float*)d_in[0];
    const float* k     = (const float*)d_in[1];
    const float* v     = (const float*)d_in[2];
    const float* dmat  = (const float*)d_in[3];
    const float* mixW1 = (const float*)d_in[4];
    const float* mixb1 = (const float*)d_in[5];
    const float* mixW2 = (const float*)d_in[6];
    const float* mixb2 = (const float*)d_in[7];
    float* out = (float*)d_out;

    size_t smem_bytes = (size_t)(BM * QS + BN * KS + BN * VS + BM * PS) * sizeof(float);
    cudaFuncSetAttribute(msdpa_kernel,
                         cudaFuncAttributeMaxDynamicSharedMemorySize,
                         (int)smem_bytes);

    dim3 grid(M_ / BM, H_, B_);   // (8, 8, 8)
    msdpa_kernel<<<grid, THREADS, smem_bytes>>>(q, k, v, dmat,
                                                mixW1, mixb1, mixW2, mixb2, out);
}

// round 6
// speedup vs baseline: 1.2685x; 1.0972x over previous
#include <cuda_runtime.h>
#include <math_constants.h>

#define B_  8
#define H_  8
#define M_  512
#define N_  512
#define DD  64
#define HID 16

#define BM 64
#define BN 64
#define TM 4
#define TN 8
#define THREADS 128

// smem strides (words)
#define QS 68
#define KS 68
#define VS 68
#define PS 72   // 16B-aligned so P rows can be read as LDS.128

#define LOG2E 1.44269504088896340736f

typedef unsigned long long ull;

__device__ __forceinline__ ull fma2(ull a, ull b, ull c) {
    ull d; asm("fma.rn.f32x2 %0,%1,%2,%3;" : "=l"(d) : "l"(a), "l"(b), "l"(c)); return d;
}
__device__ __forceinline__ ull pk(float x, float y) {
    ull r; asm("mov.b64 %0,{%1,%2};" : "=l"(r) : "f"(x), "f"(y)); return r;
}
__device__ __forceinline__ void upk(ull a, float& x, float& y) {
    asm("mov.b64 {%0,%1},%2;" : "=f"(x), "=f"(y) : "l"(a));
}
__device__ __forceinline__ ull relu2(ull a) {
    float x, y; upk(a, x, y);
    x = fmaxf(x, 0.0f); y = fmaxf(y, 0.0f);
    return pk(x, y);
}

__global__ __launch_bounds__(THREADS, 2)
void msdpa_kernel(const float* __restrict__ q,
                  const float* __restrict__ k,
                  const float* __restrict__ v,
                  const float* __restrict__ dmat,
                  const float* __restrict__ mixW1,
                  const float* __restrict__ mixb1,
                  const float* __restrict__ mixW2,
                  const float* __restrict__ mixb2,
                  float* __restrict__ out)
{
    extern __shared__ float smem[];
    float* Qs = smem;                 // [BM][QS]
    float* Ks = Qs + BM * QS;         // [BN][KS]
    float* Vs = Ks + BN * KS;         // [BN][VS]
    float* Ps = Vs + BN * VS;         // [BM][PS]

    // packed MLP weights (log2e folded into w2,b2): per f {w1s*scale, w1d, b1, w2'} dup'd
    __shared__ __align__(16) float sWp[HID * 8];
    __shared__ float sB2;

    const int tid = threadIdx.x;
    const int tx  = tid & 7;      // 0..7
    const int ty  = tid >> 3;     // 0..15  (rows ty*4+i)

    const int b  = blockIdx.z;
    const int h  = blockIdx.y;
    const int m0 = blockIdx.x * BM;

    const float* qb = q + ((size_t)(b * H_ + h) * M_ + m0) * DD;
    const float* kb = k + (size_t)(b * H_ + h) * N_ * DD;
    const float* vb = v + (size_t)(b * H_ + h) * N_ * DD;
    const float* db = dmat + ((size_t)b * M_ + m0) * N_;

    if (tid < HID) {
        const float scale = 0.125f;   // 1/sqrt(64) folded into score-channel W1
        float a = mixW1[(h * 2 + 0) * HID + tid] * scale;
        float c = mixW1[(h * 2 + 1) * HID + tid];
        float e = mixb1[h * HID + tid];
        float w = mixW2[h * HID + tid] * LOG2E;   // exp2-domain
        float* wp = sWp + tid * 8;
        wp[0] = a; wp[1] = a;
        wp[2] = c; wp[3] = c;
        wp[4] = e; wp[5] = e;
        wp[6] = w; wp[7] = w;
    }
    if (tid == 0) sB2 = mixb2[h] * LOG2E;

    // Load Q tile [BM][DD] -> Qs
    #pragma unroll
    for (int r = 0; r < 8; r++) {
        int idx = tid + r * THREADS;
        int row = idx >> 4;
        int d4  = (idx & 15) << 2;
        *(float4*)(Qs + row * QS + d4) = *(const float4*)(qb + row * DD + d4);
    }

    // O accumulators: thread owns cols {4tx+0..3} (j2=0,1) and {4tx+32..35} (j2=2,3)
    ull Oacc2[TM][4];
    float rsum[TM];
    #pragma unroll
    for (int i = 0; i < TM; i++) {
        rsum[i] = 0.0f;
        #pragma unroll
        for (int j2 = 0; j2 < 4; j2++) Oacc2[i][j2] = 0ull;
    }

    __syncthreads();

    const unsigned FULL = 0xffffffffu;
    const float B2 = sB2;

    for (int t = 0; t < N_ / BN; t++) {
        // ---- stage K, V tiles ----
        const float* kt = kb + (size_t)t * BN * DD;
        const float* vt = vb + (size_t)t * BN * DD;
        #pragma unroll
        for (int r = 0; r < 8; r++) {
            int idx = tid + r * THREADS;
            int row = idx >> 4;
            int d4  = (idx & 15) << 2;
            *(float4*)(Ks + row * KS + d4) = *(const float4*)(kt + row * DD + d4);
            *(float4*)(Vs + row * VS + d4) = *(const float4*)(vt + row * DD + d4);
        }
        __syncthreads();

        // ---- S = Q K^T (FFMA2, d-parity pairs). S cols: tx + 8j ----
        ull s2[TM][TN];
        #pragma unroll
        for (int i = 0; i < TM; i++)
            #pragma unroll
            for (int j = 0; j < TN; j++) s2[i][j] = 0ull;

        #pragma unroll 4
        for (int d4 = 0; d4 < DD; d4 += 4) {
            ulonglong2 qv[TM], kv[TN];
            #pragma unroll
            for (int i = 0; i < TM; i++)
                qv[i] = *(const ulonglong2*)(Qs + (ty * TM + i) * QS + d4);
            #pragma unroll
            for (int j = 0; j < TN; j++)
                kv[j] = *(const ulonglong2*)(Ks + (tx + 8 * j) * KS + d4);
            #pragma unroll
            for (int i = 0; i < TM; i++)
                #pragma unroll
                for (int j = 0; j < TN; j++) {
                    s2[i][j] = fma2(qv[i].x, kv[j].x, s2[i][j]);
                    s2[i][j] = fma2(qv[i].y, kv[j].y, s2[i][j]);
                }
        }

        // ---- pair-reduce, dmat, packed MLP; pairs hold S cols (tx+16j2, tx+8+16j2) ----
        ull ms2[TM][4], dm2[TM][4], acc2[TM][4];
        const ull b2p = pk(B2, B2);
        #pragma unroll
        for (int i = 0; i < TM; i++) {
            #pragma unroll
            for (int j2 = 0; j2 < 4; j2++) {
                float x0, y0, x1, y1;
                upk(s2[i][2 * j2],     x0, y0);
                upk(s2[i][2 * j2 + 1], x1, y1);
                ms2[i][j2] = pk(x0 + y0, x1 + y1);
            }
            const float* drow = db + (size_t)(ty * TM + i) * N_ + t * BN + tx;
            #pragma unroll
            for (int j2 = 0; j2 < 4; j2++)
                dm2[i][j2] = pk(drow[(2 * j2) * 8], drow[(2 * j2 + 1) * 8]);
            #pragma unroll
            for (int j2 = 0; j2 < 4; j2++) acc2[i][j2] = b2p;
        }

        #pragma unroll 4
        for (int f = 0; f < HID; f++) {
            const ull a2 = *(const ull*)(sWp + f * 8 + 0);
            const ull c2 = *(const ull*)(sWp + f * 8 + 2);
            const ull e2 = *(const ull*)(sWp + f * 8 + 4);
            const ull w2 = *(const ull*)(sWp + f * 8 + 6);
            #pragma unroll
            for (int i = 0; i < TM; i++)
                #pragma unroll
                for (int j2 = 0; j2 < 4; j2++) {
                    ull t2 = fma2(a2, ms2[i][j2], fma2(c2, dm2[i][j2], e2));
                    acc2[i][j2] = fma2(w2, relu2(t2), acc2[i][j2]);
                }
        }

        // ---- UNNORMALIZED softmax: p = exp2(acc); no max, no shuffles, no rescale ----
        #pragma unroll
        for (int i = 0; i < TM; i++) {
            float p[TN];
            #pragma unroll
            for (int j2 = 0; j2 < 4; j2++)
                upk(acc2[i][j2], p[2 * j2], p[2 * j2 + 1]);
            // p[2j2] -> col tx+8*(2j2), p[2j2+1] -> col tx+8*(2j2+1)

            float ls = 0.0f;
            #pragma unroll
            for (int j = 0; j < TN; j++) {
                p[j] = exp2f(p[j]);
                ls += p[j];
            }
            rsum[i] += ls;   // local partial; cross-lane reduce deferred to end

            float* prow = Ps + (ty * TM + i) * PS;
            #pragma unroll
            for (int j = 0; j < TN; j++)
                prow[tx + 8 * j] = p[j];
        }
        __syncthreads();

        // ---- O += P @ V : P rows via LDS.128; V via 2x LDS.128 per n ----
        #pragma unroll 2
        for (int n4 = 0; n4 < BN; n4 += 4) {
            float4 pr[TM];
            #pragma unroll
            for (int i = 0; i < TM; i++)
                pr[i] = *(const float4*)(Ps + (ty * TM + i) * PS + n4);
            float pa[TM][4];
            #pragma unroll
            for (int i = 0; i < TM; i++) {
                pa[i][0] = pr[i].x; pa[i][1] = pr[i].y;
                pa[i][2] = pr[i].z; pa[i][3] = pr[i].w;
            }
            #pragma unroll
            for (int s = 0; s < 4; s++) {
                const int n = n4 + s;
                ulonglong2 va = *(const ulonglong2*)(Vs + n * VS + 4 * tx);
                ulonglong2 vb2 = *(const ulonglong2*)(Vs + n * VS + 4 * tx + 32);
                #pragma unroll
                for (int i = 0; i < TM; i++) {
                    ull pp = pk(pa[i][s], pa[i][s]);
                    Oacc2[i][0] = fma2(pp, va.x,  Oacc2[i][0]);
                    Oacc2[i][1] = fma2(pp, va.y,  Oacc2[i][1]);
                    Oacc2[i][2] = fma2(pp, vb2.x, Oacc2[i][2]);
                    Oacc2[i][3] = fma2(pp, vb2.y, Oacc2[i][3]);
                }
            }
        }
        __syncthreads();
    }

    // ---- final cross-lane row-sum (once), normalize, store float4 ----
    float* ob = out + ((size_t)(b * H_ + h) * M_ + m0) * DD;
    #pragma unroll
    for (int i = 0; i < TM; i++) {
        float s = rsum[i];
        s += __shfl_xor_sync(FULL, s, 1, 8);
        s += __shfl_xor_sync(FULL, s, 2, 8);
        s += __shfl_xor_sync(FULL, s, 4, 8);
        float inv = 1.0f / s;

        float o[8];
        #pragma unroll
        for (int j2 = 0; j2 < 4; j2++) {
            float x, y; upk(Oacc2[i][j2], x, y);
            o[2 * j2]     = x * inv;
            o[2 * j2 + 1] = y * inv;
        }
        float* orow = ob + (size_t)(ty * TM + i) * DD;
        *(float4*)(orow + 4 * tx)      = make_float4(o[0], o[1], o[2], o[3]);
        *(float4*)(orow + 4 * tx + 32) = make_float4(o[4], o[5], o[6], o[7]);
    }
}

extern "C" void kernel_launch(void* const* d_in, const int* in_sizes, int n_in,
                              void* d_out, int out_size)
{
    const float* q     = (const float*)d_in[0];
    const float* k     = (const float*)d_in[1];
    const float* v     = (const float*)d_in[2];
    const float* dmat  = (const float*)d_in[3];
    const float* mixW1 = (const float*)d_in[4];
    const float* mixb1 = (const float*)d_in[5];
    const float* mixW2 = (const float*)d_in[6];
    const float* mixb2 = (const float*)d_in[7];
    float* out = (float*)d_out;

    size_t smem_bytes = (size_t)(BM * QS + BN * KS + BN * VS + BM * PS) * sizeof(float);
    cudaFuncSetAttribute(msdpa_kernel,
                         cudaFuncAttributeMaxDynamicSharedMemorySize,
                         (int)smem_bytes);

    dim3 grid(M_ / BM, H_, B_);   // (8, 8, 8)
    msdpa_kernel<<<grid, THREADS, smem_bytes>>>(q, k, v, dmat,
                                                mixW1, mixb1, mixW2, mixb2, out);
}

// round 8
// speedup vs baseline: 2.0255x; 1.5967x over previous
#include <cuda_runtime.h>
#include <cuda_bf16.h>
#include <stdint.h>

#define B_  8
#define H_  8
#define M_  512
#define N_  512
#define DD  64
#define HID 16

#define BM 128
#define BN 64
#define THREADS 256
#define NTILES (N_ / BN)
#define LOG2E 1.44269504088896340736f

// smem word (u32) offsets; rows are 36 words (32 data + 4 pad) for conflict-free frags
#define W_QHI 0          // [128][36]
#define W_QLO 4608
#define W_KHI 9216       // [64][36]
#define W_KLO 11520
#define W_VTHI 13824     // V^T [64 d][36] (cols = key-pair words, XOR-swizzled)
#define W_VTLO 16128
#define SMEM_WORDS 18432
#define SMEM_BYTES (SMEM_WORDS * 4)

typedef unsigned long long ull;

__device__ __forceinline__ ull fma2(ull a, ull b, ull c) {
    ull d; asm("fma.rn.f32x2 %0,%1,%2,%3;" : "=l"(d) : "l"(a), "l"(b), "l"(c)); return d;
}
__device__ __forceinline__ ull pk(float x, float y) {
    ull r; asm("mov.b64 %0,{%1,%2};" : "=l"(r) : "f"(x), "f"(y)); return r;
}
__device__ __forceinline__ void upk(ull a, float& x, float& y) {
    asm("mov.b64 {%0,%1},%2;" : "=f"(x), "=f"(y) : "l"(a));
}
__device__ __forceinline__ ull relu2(ull a) {
    float x, y; upk(a, x, y);
    return pk(fmaxf(x, 0.0f), fmaxf(y, 0.0f));
}
// pack two f32 -> bf16x2, element x in LOW half (matches fragment col-even-in-low)
__device__ __forceinline__ uint32_t cvt2(float x, float y) {
    uint32_t r; asm("cvt.rn.bf16x2.f32 %0, %1, %2;" : "=r"(r) : "f"(y), "f"(x)); return r;
}
__device__ __forceinline__ float lo16f(uint32_t w) { return __uint_as_float(w << 16); }
__device__ __forceinline__ float hi16f(uint32_t w) { return __uint_as_float(w & 0xffff0000u); }

// D += A * B   (m16n8k16, bf16 in, f32 accum)
__device__ __forceinline__ void mma16816(float* d, const uint32_t* a, uint32_t b0, uint32_t b1) {
    asm volatile(
        "mma.sync.aligned.m16n8k16.row.col.f32.bf16.bf16.f32 "
        "{%0,%1,%2,%3}, {%4,%5,%6,%7}, {%8,%9}, {%0,%1,%2,%3};"
        : "+f"(d[0]), "+f"(d[1]), "+f"(d[2]), "+f"(d[3])
        : "r"(a[0]), "r"(a[1]), "r"(a[2]), "r"(a[3]), "r"(b0), "r"(b1));
}

__global__ __launch_bounds__(THREADS, 2)
void msdpa_mma_kernel(const float* __restrict__ q,
                      const float* __restrict__ k,
                      const float* __restrict__ v,
                      const float* __restrict__ dmat,
                      const float* __restrict__ mixW1,
                      const float* __restrict__ mixb1,
                      const float* __restrict__ mixW2,
                      const float* __restrict__ mixb2,
                      float* __restrict__ out)
{
    extern __shared__ uint32_t sm[];
    uint32_t* Qhi = sm + W_QHI;
    uint32_t* Qlo = sm + W_QLO;
    uint32_t* Khi = sm + W_KHI;
    uint32_t* Klo = sm + W_KLO;
    uint32_t* Vthi = sm + W_VTHI;
    uint32_t* Vtlo = sm + W_VTLO;

    __shared__ __align__(16) float sWp[HID * 8];
    __shared__ float sB2;

    const int tid  = threadIdx.x;
    const int wid  = tid >> 5;
    const int lane = tid & 31;
    const int g    = lane >> 2;     // group-of-4 id: fragment row
    const int tig  = lane & 3;      // thread-in-group: fragment col pair

    const int b  = blockIdx.z;
    const int h  = blockIdx.y;
    const int m0 = blockIdx.x * BM;

    const float* qb = q + ((size_t)(b * H_ + h) * M_ + m0) * DD;
    const float* kb = k + (size_t)(b * H_ + h) * N_ * DD;
    const float* vb = v + (size_t)(b * H_ + h) * N_ * DD;

    // MLP weights: scale folded into score channel; log2e into w2/b2; dup pairs
    if (tid < HID) {
        const float scale = 0.125f;
        float a = mixW1[(h * 2 + 0) * HID + tid] * scale;
        float c = mixW1[(h * 2 + 1) * HID + tid];
        float e = mixb1[h * HID + tid];
        float w = mixW2[h * HID + tid] * LOG2E;
        float* wp = sWp + tid * 8;
        wp[0] = a; wp[1] = a; wp[2] = c; wp[3] = c;
        wp[4] = e; wp[5] = e; wp[6] = w; wp[7] = w;
    }
    if (tid == 0) sB2 = mixb2[h] * LOG2E;

    // ---- stage Q (hi/lo split) once: [128 rows][32 words], stride 36 ----
    {
        int row = tid >> 1;
        int c0  = (tid & 1) * 16;    // word col base
        const float* qr = qb + row * DD + (tid & 1) * 32;
        #pragma unroll
        for (int i = 0; i < 8; i++) {
            float4 f = ((const float4*)qr)[i];
            uint32_t h0 = cvt2(f.x, f.y);
            uint32_t l0 = cvt2(f.x - lo16f(h0), f.y - hi16f(h0));
            uint32_t h1 = cvt2(f.z, f.w);
            uint32_t l1 = cvt2(f.z - lo16f(h1), f.w - hi16f(h1));
            int w = row * 36 + c0 + i * 2;
            Qhi[w] = h0; Qhi[w + 1] = h1;
            Qlo[w] = l0; Qlo[w + 1] = l1;
        }
    }

    float Od[8][4];
    #pragma unroll
    for (int d = 0; d < 8; d++)
        #pragma unroll
        for (int e = 0; e < 4; e++) Od[d][e] = 0.0f;
    float rs0 = 0.0f, rs1 = 0.0f;

    __syncthreads();
    const ull b2p = pk(sB2, sB2);

    const int r0w = (wid * 16 + g) * 36;      // Q word base, row r0
    const int r1w = r0w + 8 * 36;             // row r0+8
    const float* dm0 = dmat + ((size_t)b * M_ + m0 + wid * 16 + g) * N_;

    for (int t = 0; t < NTILES; t++) {
        // ---- stage K tile [64][64] hi/lo ----
        {
            int key = tid >> 2;
            int c0  = (tid & 3) * 8;
            const float* kr = kb + (size_t)(t * BN + key) * DD + (tid & 3) * 16;
            #pragma unroll
            for (int i = 0; i < 4; i++) {
                float4 f = ((const float4*)kr)[i];
                uint32_t h0 = cvt2(f.x, f.y);
                uint32_t l0 = cvt2(f.x - lo16f(h0), f.y - hi16f(h0));
                uint32_t h1 = cvt2(f.z, f.w);
                uint32_t l1 = cvt2(f.z - lo16f(h1), f.w - hi16f(h1));
                int w = key * 36 + c0 + i * 2;
                Khi[w] = h0; Khi[w + 1] = h1;
                Klo[w] = l0; Klo[w + 1] = l1;
            }
        }
        // ---- stage V^T tile: Vt[d][keypair-word], col XOR-swizzled by (d>>3)<<2 ----
        {
            int kp = tid >> 3;            // key pair 0..31
            int a  = tid & 7;             // d-octet
            int d0 = a * 8;
            const float* v0 = vb + (size_t)(t * BN + 2 * kp) * DD + d0;
            const float* v1 = v0 + DD;
            float4 f0a = ((const float4*)v0)[0], f0b = ((const float4*)v0)[1];
            float4 f1a = ((const float4*)v1)[0], f1b = ((const float4*)v1)[1];
            float e0[8] = {f0a.x, f0a.y, f0a.z, f0a.w, f0b.x, f0b.y, f0b.z, f0b.w};
            float e1[8] = {f1a.x, f1a.y, f1a.z, f1a.w, f1b.x, f1b.y, f1b.z, f1b.w};
            int colp = kp ^ (a << 2);
            #pragma unroll
            for (int i = 0; i < 8; i++) {
                uint32_t hw = cvt2(e0[i], e1[i]);   // lo: key 2kp, hi: key 2kp+1
                uint32_t lw = cvt2(e0[i] - lo16f(hw), e1[i] - hi16f(hw));
                Vthi[(d0 + i) * 36 + colp] = hw;
                Vtlo[(d0 + i) * 36 + colp] = lw;
            }
        }
        __syncthreads();

        // ---- S = Q K^T via 3-product split mma ----
        float S[8][4];
        #pragma unroll
        for (int n = 0; n < 8; n++)
            #pragma unroll
            for (int e = 0; e < 4; e++) S[n][e] = 0.0f;

        #pragma unroll
        for (int kc = 0; kc < 4; kc++) {
            int wq = kc * 8 + tig;
            uint32_t qh[4] = {Qhi[r0w + wq], Qhi[r1w + wq], Qhi[r0w + wq + 4], Qhi[r1w + wq + 4]};
            uint32_t ql[4] = {Qlo[r0w + wq], Qlo[r1w + wq], Qlo[r0w + wq + 4], Qlo[r1w + wq + 4]};
            #pragma unroll
            for (int n = 0; n < 8; n++) {
                int wb = (n * 8 + g) * 36 + kc * 8 + tig;
                uint32_t bh0 = Khi[wb], bh1 = Khi[wb + 4];
                uint32_t bl0 = Klo[wb], bl1 = Klo[wb + 4];
                mma16816(S[n], qh, bh0, bh1);
                mma16816(S[n], qh, bl0, bl1);
                mma16816(S[n], ql, bh0, bh1);
            }
        }

        // ---- MLP + exp2 (unnormalized) + P fragments in registers ----
        uint32_t PhiA[8], PhiB[8], PloA[8], PloB[8];
        #pragma unroll
        for (int n = 0; n < 8; n++) {
            int col = t * BN + n * 8 + tig * 2;
            float2 dA = *(const float2*)(dm0 + col);
            float2 dB = *(const float2*)(dm0 + 8 * N_ + col);
            ull ms01 = pk(S[n][0], S[n][1]);
            ull ms23 = pk(S[n][2], S[n][3]);
            ull dm01 = pk(dA.x, dA.y);
            ull dm23 = pk(dB.x, dB.y);
            ull a01 = b2p, a23 = b2p;
            #pragma unroll
            for (int f = 0; f < HID; f++) {
                const ull w1s = *(const ull*)(sWp + f * 8 + 0);
                const ull w1d = *(const ull*)(sWp + f * 8 + 2);
                const ull bb  = *(const ull*)(sWp + f * 8 + 4);
                const ull w2  = *(const ull*)(sWp + f * 8 + 6);
                a01 = fma2(w2, relu2(fma2(w1s, ms01, fma2(w1d, dm01, bb))), a01);
                a23 = fma2(w2, relu2(fma2(w1s, ms23, fma2(w1d, dm23, bb))), a23);
            }
            float p0, p1, p2, p3;
            upk(a01, p0, p1); upk(a23, p2, p3);
            p0 = exp2f(p0); p1 = exp2f(p1); p2 = exp2f(p2); p3 = exp2f(p3);
            rs0 += p0 + p1;
            rs1 += p2 + p3;
            uint32_t hA = cvt2(p0, p1);
            PhiA[n] = hA;
            PloA[n] = cvt2(p0 - lo16f(hA), p1 - hi16f(hA));
            uint32_t hB = cvt2(p2, p3);
            PhiB[n] = hB;
            PloB[n] = cvt2(p2 - lo16f(hB), p3 - hi16f(hB));
        }

        // ---- O += P V via 3-product split mma (P frags straight from registers) ----
        #pragma unroll
        for (int kc = 0; kc < 4; kc++) {
            uint32_t ah[4] = {PhiA[2 * kc], PhiB[2 * kc], PhiA[2 * kc + 1], PhiB[2 * kc + 1]};
            uint32_t al[4] = {PloA[2 * kc], PloB[2 * kc], PloA[2 * kc + 1], PloB[2 * kc + 1]};
            #pragma unroll
            for (int dt = 0; dt < 8; dt++) {
                int row = dt * 8 + g;
                int w0 = row * 36 + ((kc * 8 + tig) ^ (dt << 2));
                int w1 = row * 36 + ((kc * 8 + tig + 4) ^ (dt << 2));
                uint32_t bh0 = Vthi[w0], bh1 = Vthi[w1];
                uint32_t bl0 = Vtlo[w0], bl1 = Vtlo[w1];
                mma16816(Od[dt], ah, bh0, bh1);
                mma16816(Od[dt], ah, bl0, bl1);
                mma16816(Od[dt], al, bh0, bh1);
            }
        }
        __syncthreads();
    }

    // ---- epilogue: quad-reduce row sums, normalize, store ----
    const unsigned FULL = 0xffffffffu;
    rs0 += __shfl_xor_sync(FULL, rs0, 1);
    rs0 += __shfl_xor_sync(FULL, rs0, 2);
    rs1 += __shfl_xor_sync(FULL, rs1, 1);
    rs1 += __shfl_xor_sync(FULL, rs1, 2);
    float i0 = 1.0f / rs0;
    float i1 = 1.0f / rs1;

    float* o0 = out + ((size_t)(b * H_ + h) * M_ + m0 + wid * 16 + g) * DD;
    float* o1 = o0 + 8 * DD;
    #pragma unroll
    for (int dt = 0; dt < 8; dt++) {
        *(float2*)(o0 + dt * 8 + tig * 2) = make_float2(Od[dt][0] * i0, Od[dt][1] * i0);
        *(float2*)(o1 + dt * 8 + tig * 2) = make_float2(Od[dt][2] * i1, Od[dt][3] * i1);
    }
}

extern "C" void kernel_launch(void* const* d_in, const int* in_sizes, int n_in,
                              void* d_out, int out_size)
{
    const float* q     = (const float*)d_in[0];
    const float* k     = (const float*)d_in[1];
    const float* v     = (const float*)d_in[2];
    const float* dmat  = (const float*)d_in[3];
    const float* mixW1 = (const float*)d_in[4];
    const float* mixb1 = (const float*)d_in[5];
    const float* mixW2 = (const float*)d_in[6];
    const float* mixb2 = (const float*)d_in[7];
    float* out = (float*)d_out;

    cudaFuncSetAttribute(msdpa_mma_kernel,
                         cudaFuncAttributeMaxDynamicSharedMemorySize, SMEM_BYTES);

    dim3 grid(M_ / BM, H_, B_);   // (4, 8, 8)
    msdpa_mma_kernel<<<grid, THREADS, SMEM_BYTES>>>(q, k, v, dmat,
                                                    mixW1, mixb1, mixW2, mixb2, out);
}